// round 2
// baseline (speedup 1.0000x reference)
#include <cuda_runtime.h>
#include <cuda_bf16.h>
#include <cstdint>
#include <cstdio>

// ---------------- problem constants ----------------
#define NROWS   8192
#define DDIM    256
#define HALF_N  4096

// ---------------- tiling ----------------
#define TM      128                   // rows per CTA
#define TN      64                    // cols per B tile
#define CS      2                     // column splits
#define COLS_PER_CTA (NROWS / CS)     // 4096
#define NTILES  (COLS_PER_CTA / TN)   // 64

#define SAS     264                   // padded row stride in bf16 elems (528B, 16B-aligned, conflict-free)
#define SA_BYTES (TM * SAS * 2)       // 67584
#define SB_BYTES (TN * SAS * 2)       // 33792
#define SUMS_OFF (SA_BYTES + 2 * SB_BYTES)
#define SMEM_BYTES (SUMS_OFF + TM * 2 * (int)sizeof(float))

// 2 * log2(e): exp(2*c) = 2^(c * 2*log2 e)
#define TWO_LOG2E 2.8853900817779268f

// ---------------- device scratch (no allocations allowed) ----------------
__device__ __align__(16) __nv_bfloat16 g_zn[NROWS * DDIM];
__device__ float g_pos[NROWS];
__device__ float g_S[NROWS * CS];

// ---------------- helpers ----------------
__device__ __forceinline__ void cp16(void* dst_smem, const void* src_gmem) {
    uint32_t d = (uint32_t)__cvta_generic_to_shared(dst_smem);
    asm volatile("cp.async.cg.shared.global [%0], [%1], 16;" :: "r"(d), "l"(src_gmem));
}

// ---------------- kernel 1: normalize rows, fp32 -> bf16 ----------------
__global__ __launch_bounds__(256) void k_normalize(const float* __restrict__ zi,
                                                   const float* __restrict__ zj) {
    int warp = threadIdx.x >> 5, lane = threadIdx.x & 31;
    int r = blockIdx.x * 8 + warp;
    const float* src = (r < HALF_N) ? (zi + (size_t)r * DDIM)
                                    : (zj + (size_t)(r - HALF_N) * DDIM);
    const float4* s4 = (const float4*)src;
    float4 v0 = s4[lane * 2];
    float4 v1 = s4[lane * 2 + 1];
    float ss = v0.x*v0.x + v0.y*v0.y + v0.z*v0.z + v0.w*v0.w
             + v1.x*v1.x + v1.y*v1.y + v1.z*v1.z + v1.w*v1.w;
#pragma unroll
    for (int o = 16; o; o >>= 1) ss += __shfl_xor_sync(0xffffffffu, ss, o);
    float scale = 1.0f / fmaxf(sqrtf(ss), 1e-8f);

    __nv_bfloat162 p[4];
    p[0].x = __float2bfloat16(v0.x * scale); p[0].y = __float2bfloat16(v0.y * scale);
    p[1].x = __float2bfloat16(v0.z * scale); p[1].y = __float2bfloat16(v0.w * scale);
    p[2].x = __float2bfloat16(v1.x * scale); p[2].y = __float2bfloat16(v1.y * scale);
    p[3].x = __float2bfloat16(v1.z * scale); p[3].y = __float2bfloat16(v1.w * scale);
    uint4 w;
    w.x = *reinterpret_cast<uint32_t*>(&p[0]);
    w.y = *reinterpret_cast<uint32_t*>(&p[1]);
    w.z = *reinterpret_cast<uint32_t*>(&p[2]);
    w.w = *reinterpret_cast<uint32_t*>(&p[3]);
    reinterpret_cast<uint4*>(g_zn + (size_t)r * DDIM)[lane] = w;
}

// ---------------- kernel 2: fused GEMM + sum-exp + pos capture ----------------
__global__ __launch_bounds__(256, 1) void k_gemm_lse() {
    extern __shared__ char smem[];
    __nv_bfloat16* sA  = (__nv_bfloat16*)smem;
    __nv_bfloat16* sB0 = (__nv_bfloat16*)(smem + SA_BYTES);
    __nv_bfloat16* sB1 = (__nv_bfloat16*)(smem + SA_BYTES + SB_BYTES);
    float* sums = (float*)(smem + SUMS_OFF);

    int tid = threadIdx.x;
    int lane = tid & 31, warp = tid >> 5;
    int wm = warp >> 1, wn = warp & 1;           // 4x2 warp grid, warp tile 32x32
    int cs = blockIdx.x, rt = blockIdx.y;
    int row0 = rt * TM, colBase = cs * COLS_PER_CTA;

    // stage A panel (128 x 256 bf16), 16B chunks
#pragma unroll
    for (int i = 0; i < 16; i++) {
        int id = i * 256 + tid;
        int rowl = id >> 5, cir = id & 31;
        cp16(sA + rowl * SAS + cir * 8,
             g_zn + (size_t)(row0 + rowl) * DDIM + cir * 8);
    }
    // stage B tile 0
#pragma unroll
    for (int i = 0; i < 8; i++) {
        int id = i * 256 + tid;
        int rowl = id >> 5, cir = id & 31;
        cp16(sB0 + rowl * SAS + cir * 8,
             g_zn + (size_t)(colBase + rowl) * DDIM + cir * 8);
    }
    asm volatile("cp.async.commit_group;");

    uint32_t sA32 = (uint32_t)__cvta_generic_to_shared(sA);
    uint32_t sB32[2] = {(uint32_t)__cvta_generic_to_shared(sB0),
                        (uint32_t)__cvta_generic_to_shared(sB1)};

    // ldmatrix lane bases.
    // A x4: lanes 0-15 -> rows 0..15 @ k0, lanes 16-31 -> rows 0..15 @ k0+8
    uint32_t aAddr[2];
#pragma unroll
    for (int mt = 0; mt < 2; mt++)
        aAddr[mt] = sA32 + (uint32_t)(((wm * 32 + mt * 16 + (lane & 15)) * SAS
                                       + ((lane >> 4) * 8)) * 2);
    // B x4 (pair p covers n-tiles 2p, 2p+1):
    // lanes 0-7: nt=2p @klo; 8-15: nt=2p @khi; 16-23: nt=2p+1 @klo; 24-31: nt=2p+1 @khi
    uint32_t bOff[2];
#pragma unroll
    for (int p = 0; p < 2; p++)
        bOff[p] = (uint32_t)(((wn * 32 + p * 16 + ((lane >> 4) << 3) + (lane & 7)) * SAS
                              + (((lane >> 3) & 1) * 8)) * 2);

    float rs[2][2] = {{0.f, 0.f}, {0.f, 0.f}};   // per-thread row sums (4 rows)

    for (int ct = 0; ct < NTILES; ct++) {
        int buf = ct & 1;
        if (ct + 1 < NTILES) {
            __nv_bfloat16* dstB = (ct & 1) ? sB0 : sB1;   // buffer (ct+1)&1
            int gcol0 = colBase + (ct + 1) * TN;
#pragma unroll
            for (int i = 0; i < 8; i++) {
                int id = i * 256 + tid;
                int rowl = id >> 5, cir = id & 31;
                cp16(dstB + rowl * SAS + cir * 8,
                     g_zn + (size_t)(gcol0 + rowl) * DDIM + cir * 8);
            }
            asm volatile("cp.async.commit_group;");
            asm volatile("cp.async.wait_group 1;");
        } else {
            asm volatile("cp.async.wait_group 0;");
        }
        __syncthreads();

        float c[2][4][4];
#pragma unroll
        for (int mt = 0; mt < 2; mt++)
#pragma unroll
            for (int nt = 0; nt < 4; nt++)
#pragma unroll
                for (int e = 0; e < 4; e++) c[mt][nt][e] = 0.f;

        uint32_t bBase = sB32[buf];
#pragma unroll
        for (int ks = 0; ks < 16; ks++) {
            uint32_t a[2][4];
#pragma unroll
            for (int mt = 0; mt < 2; mt++) {
                uint32_t addr = aAddr[mt] + ks * 32;
                asm volatile("ldmatrix.sync.aligned.m8n8.x4.shared.b16 {%0,%1,%2,%3}, [%4];"
                             : "=r"(a[mt][0]), "=r"(a[mt][1]), "=r"(a[mt][2]), "=r"(a[mt][3])
                             : "r"(addr));
            }
            uint32_t b[4][2];
#pragma unroll
            for (int p = 0; p < 2; p++) {
                uint32_t addr = bBase + bOff[p] + ks * 32;
                asm volatile("ldmatrix.sync.aligned.m8n8.x4.shared.b16 {%0,%1,%2,%3}, [%4];"
                             : "=r"(b[2*p][0]), "=r"(b[2*p][1]), "=r"(b[2*p+1][0]), "=r"(b[2*p+1][1])
                             : "r"(addr));
            }
#pragma unroll
            for (int mt = 0; mt < 2; mt++)
#pragma unroll
                for (int nt = 0; nt < 4; nt++)
                    asm volatile("mma.sync.aligned.m16n8k16.row.col.f32.bf16.bf16.f32 "
                                 "{%0,%1,%2,%3}, {%4,%5,%6,%7}, {%8,%9}, {%0,%1,%2,%3};"
                                 : "+f"(c[mt][nt][0]), "+f"(c[mt][nt][1]),
                                   "+f"(c[mt][nt][2]), "+f"(c[mt][nt][3])
                                 : "r"(a[mt][0]), "r"(a[mt][1]), "r"(a[mt][2]), "r"(a[mt][3]),
                                   "r"(b[nt][0]), "r"(b[nt][1]));
        }

        // epilogue: exp, diag mask, pos capture, row accumulate
        int gcol0 = colBase + ct * TN;
#pragma unroll
        for (int mt = 0; mt < 2; mt++) {
#pragma unroll
            for (int hi = 0; hi < 2; hi++) {
                int i = row0 + wm * 32 + mt * 16 + (lane >> 2) + hi * 8;
                int ipart = i ^ HALF_N;
                float acc = 0.f;
#pragma unroll
                for (int nt = 0; nt < 4; nt++) {
#pragma unroll
                    for (int lo = 0; lo < 2; lo++) {
                        float cv = c[mt][nt][hi * 2 + lo];
                        int j = gcol0 + wn * 32 + nt * 8 + ((lane & 3) << 1) + lo;
                        float ev;
                        asm("ex2.approx.f32 %0, %1;" : "=f"(ev) : "f"(cv * TWO_LOG2E));
                        if (j == i) ev = 0.f;              // mask self-diagonal
                        if (j == ipart) g_pos[i] = 2.0f * cv;  // positive logit
                        acc += ev;
                    }
                }
                rs[mt][hi] += acc;
            }
        }
        __syncthreads();   // protect smem buffers before next prefetch overwrites
    }

    // reduce per-row sums: quad shuffle, then combine the two wn warps via smem
#pragma unroll
    for (int mt = 0; mt < 2; mt++)
#pragma unroll
        for (int hi = 0; hi < 2; hi++) {
            float v = rs[mt][hi];
            v += __shfl_xor_sync(0xffffffffu, v, 1);
            v += __shfl_xor_sync(0xffffffffu, v, 2);
            if ((lane & 3) == 0) {
                int rl = wm * 32 + mt * 16 + (lane >> 2) + hi * 8;
                sums[rl * 2 + wn] = v;
            }
        }
    __syncthreads();
    if (tid < TM) {
        float S = sums[tid * 2] + sums[tid * 2 + 1];
        g_S[(size_t)(row0 + tid) * CS + cs] = S;
    }
}

// ---------------- kernel 3: deterministic final reduction ----------------
__global__ __launch_bounds__(256) void k_finalize(float* __restrict__ out) {
    __shared__ float red[256];
    int tid = threadIdx.x;
    float acc = 0.f;
    for (int r = tid; r < NROWS; r += 256) {
        float S = g_S[r * CS] + g_S[r * CS + 1];
        acc += logf(S) - g_pos[r];
    }
    red[tid] = acc;
    __syncthreads();
#pragma unroll
    for (int s = 128; s > 0; s >>= 1) {
        if (tid < s) red[tid] += red[tid + s];
        __syncthreads();
    }
    if (tid == 0) out[0] = red[0] * (1.0f / (float)NROWS);
}

// ---------------- launcher ----------------
extern "C" void kernel_launch(void* const* d_in, const int* in_sizes, int n_in,
                              void* d_out, int out_size) {
    (void)in_sizes; (void)n_in; (void)out_size;
    const float* zi = (const float*)d_in[0];
    const float* zj = (const float*)d_in[1];
    float* out = (float*)d_out;

    cudaFuncSetAttribute((const void*)k_gemm_lse,
                         cudaFuncAttributeMaxDynamicSharedMemorySize, SMEM_BYTES);

    k_normalize<<<NROWS / 8, 256>>>(zi, zj);
    k_gemm_lse<<<dim3(CS, NROWS / TM), 256, SMEM_BYTES>>>();
    k_finalize<<<1, 256>>>(out);
}